// round 8
// baseline (speedup 1.0000x reference)
#include <cuda_runtime.h>
#include <cuda_bf16.h>
#include <cstdint>

#define BINS   30
#define TPB    512
#define GRID   148     // 1 block per SM
#define TILE   2048    // elements per tile (24 KB: 16 KB x + 8 KB t)
#define STAGES 4

// dynamic smem layout (bytes):
//   [0, 122880)                 hist: float2[BINS*TPB]
//   [122880, 122880+65536)      xs:   float2[STAGES*TILE]
//   [188416, 188416+32768)      ts:   int[STAGES*TILE]
#define SMEM_HIST 0
#define SMEM_XS   122880
#define SMEM_TS   (SMEM_XS + STAGES * TILE * 8)
#define SMEM_TOTAL (SMEM_TS + STAGES * TILE * 4)   // 221184 B = 216 KB

__device__ float2 g_part[GRID * BINS];
__device__ unsigned int g_ctr = 0;

__device__ __forceinline__ float rcp_approx(float x) {
    float r;
    asm("rcp.approx.f32 %0, %1;" : "=f"(r) : "f"(x));
    return r;
}

__device__ __forceinline__ void cp_async16(uint32_t saddr, const void* gptr) {
    asm volatile("cp.async.cg.shared.global [%0], [%1], 16;" :: "r"(saddr), "l"(gptr));
}
__device__ __forceinline__ void cp_commit() {
    asm volatile("cp.async.commit_group;");
}
template <int N>
__device__ __forceinline__ void cp_wait() {
    asm volatile("cp.async.wait_group %0;" :: "n"(N));
}

// u = x_other - x_true.  g = sigmoid(u),  ce = log(1+e^u).
__device__ __forceinline__ void ghm_elem(float x0, float x1, int t, float2* hrow) {
    float diff = x1 - x0;
    float u = __int_as_float(__float_as_int(diff) ^ (t << 31));
    float e = __expf(u);
    float s = 1.0f + e;
    float r = rcp_approx(s);
    float bin_f = fmaf(r, -30.0f, 30.0f);     // 30 * (1 - 1/s) = 30*g
    bin_f = fminf(bin_f, 29.0f);
    int bin = (int)bin_f;
    float lg = __log2f(s);

    float2 h = hrow[bin * TPB];
    h.x += 1.0f;
    h.y = fmaf(lg, 0.69314718056f, h.y);      // ce = lg * ln2
    hrow[bin * TPB] = h;
}

// issue cp.asyncs for tile T into stage st (predicated on T < NT); always commits.
__device__ __forceinline__ void issue_tile(const float4* __restrict__ x4,
                                           const int4* __restrict__ t4,
                                           int T, int NT, int st, int tid,
                                           uint32_t xs_s, uint32_t ts_s) {
    if (T < NT) {
        // x: TILE float2 = TILE/2 float4 = 1024 -> 2 per thread
        const float4* xg = x4 + (size_t)T * (TILE / 2);
        uint32_t xd = xs_s + (uint32_t)(st * TILE) * 8u;
        #pragma unroll
        for (int j = 0; j < TILE / 2 / TPB; j++) {
            int i = tid + j * TPB;
            cp_async16(xd + i * 16u, xg + i);
        }
        // t: TILE ints = TILE/4 int4 = 512 -> 1 per thread
        const int4* tg = t4 + (size_t)T * (TILE / 4);
        uint32_t td = ts_s + (uint32_t)(st * TILE) * 4u;
        if (tid < TILE / 4) cp_async16(td + tid * 16u, tg + tid);
    }
    cp_commit();
}

__global__ void __launch_bounds__(TPB, 1) ghm_fused(const float4* __restrict__ x4,
                                                    const int4* __restrict__ t4,
                                                    const float2* __restrict__ x2,
                                                    const int* __restrict__ tgt,
                                                    int B,
                                                    float* __restrict__ out,
                                                    int out_size) {
    extern __shared__ char smem[];
    float2* hist = (float2*)(smem + SMEM_HIST);
    float2* xs   = (float2*)(smem + SMEM_XS);
    int*    ts   = (int*)(smem + SMEM_TS);
    uint32_t xs_s = (uint32_t)__cvta_generic_to_shared(xs);
    uint32_t ts_s = (uint32_t)__cvta_generic_to_shared(ts);

    int tid = threadIdx.x;
    int bx  = blockIdx.x;

    #pragma unroll
    for (int b = 0; b < BINS; b++) hist[b * TPB + tid] = make_float2(0.0f, 0.0f);
    __syncthreads();

    float2* hrow = &hist[tid];

    int NT = B / TILE;   // full tiles

    // prologue: fill all four stages
    #pragma unroll
    for (int p = 0; p < STAGES; p++)
        issue_tile(x4, t4, bx + p * GRID, NT, p, tid, xs_s, ts_s);

    // steady state: while computing tile k, tiles k+1..k+3 are in flight (72KB/SM)
    for (int k = 0; ; k++) {
        int T = bx + k * GRID;
        if (T >= NT) break;
        int st = k & (STAGES - 1);

        cp_wait<STAGES - 1>();   // this thread's part of tile k done
        __syncthreads();         // whole tile visible

        float2* xst = xs + st * TILE;
        int*    tst = ts + st * TILE;
        #pragma unroll
        for (int j = 0; j < TILE / TPB; j++) {   // 4 elements per thread
            int i = tid + j * TPB;
            float2 xv = xst[i];
            int    tv = tst[i];
            ghm_elem(xv.x, xv.y, tv, hrow);
        }

        __syncthreads();         // stage fully consumed before refill
        issue_tile(x4, t4, bx + (k + STAGES) * GRID, NT, st, tid, xs_s, ts_s);
    }
    cp_wait<0>();

    // tail (B % TILE, zero for this shape)
    int gt = bx * TPB + tid;
    for (int j = NT * TILE + gt; j < B; j += GRID * TPB) {
        float2 xv = x2[j];
        ghm_elem(xv.x, xv.y, tgt[j], hrow);
    }

    __syncthreads();

    // tree-reduce columns per bin
    for (int s = TPB / 2; s > 0; s >>= 1) {
        if (tid < s) {
            #pragma unroll
            for (int b = 0; b < BINS; b++) {
                float2 p = hist[b * TPB + tid];
                float2 q = hist[b * TPB + tid + s];
                p.x += q.x; p.y += q.y;
                hist[b * TPB + tid] = p;
            }
        }
        __syncthreads();
    }

    // per-block partials + last-block finalize
    if (tid < BINS) g_part[bx * BINS + tid] = hist[tid * TPB];
    __threadfence();
    __syncthreads();

    __shared__ bool is_last;
    if (tid == 0) {
        unsigned prev = atomicAdd(&g_ctr, 1u);
        is_last = (prev == GRID - 1);
    }
    __syncthreads();
    if (!is_last) return;

    __threadfence();

    #pragma unroll
    for (int b = 0; b < BINS; b++) hist[b * TPB + tid] = make_float2(0.0f, 0.0f);
    __syncthreads();

    for (int i = tid; i < GRID * BINS; i += TPB) {
        float2 v = g_part[i];
        int b = i % BINS;
        float2 h = hrow[b * TPB];
        h.x += v.x; h.y += v.y;
        hrow[b * TPB] = h;
    }
    __syncthreads();

    for (int s = TPB / 2; s > 0; s >>= 1) {
        if (tid < s) {
            #pragma unroll
            for (int b = 0; b < BINS; b++) {
                float2 p = hist[b * TPB + tid];
                float2 q = hist[b * TPB + tid + s];
                p.x += q.x; p.y += q.y;
                hist[b * TPB + tid] = p;
            }
        }
        __syncthreads();
    }

    if (tid < 32) {
        float cnt = (tid < BINS) ? hist[tid * TPB].x : 0.0f;
        float ces = (tid < BINS) ? hist[tid * TPB].y : 0.0f;
        float nz   = (cnt > 0.0f) ? 1.0f : 0.0f;
        float term = (cnt > 0.0f) ? ces / (0.25f * cnt) : 0.0f;
        #pragma unroll
        for (int o = 16; o > 0; o >>= 1) {
            nz   += __shfl_xor_sync(0xFFFFFFFFu, nz,   o);
            term += __shfl_xor_sync(0xFFFFFFFFu, term, o);
        }
        if (tid == 0) {
            float loss = term / fmaxf(nz, 1.0f);
            for (int i = 0; i < out_size; i++) out[i] = loss;
            g_ctr = 0;  // reset for next graph replay
        }
    }
}

extern "C" void kernel_launch(void* const* d_in, const int* in_sizes, int n_in,
                              void* d_out, int out_size) {
    const float* x   = (const float*)d_in[0];
    const int*   tgt = (const int*)d_in[1];
    int B = in_sizes[1];   // target element count == batch size

    cudaFuncSetAttribute(ghm_fused, cudaFuncAttributeMaxDynamicSharedMemorySize, SMEM_TOTAL);
    ghm_fused<<<GRID, TPB, SMEM_TOTAL>>>((const float4*)x, (const int4*)tgt,
                                         (const float2*)x, tgt, B,
                                         (float*)d_out, out_size);
}

// round 9
// speedup vs baseline: 1.2499x; 1.2499x over previous
#include <cuda_runtime.h>
#include <cuda_bf16.h>
#include <cstdint>

#define BINS   30
#define TPB    256
#define GRID   296     // 2 blocks per SM
#define TILE   1024    // elements per tile (12 KB: 8 KB x + 4 KB t)
#define STAGES 3
#define EPT    (TILE / TPB)   // 4 elements per thread per tile

// dynamic smem layout (bytes):
//   [0, 61440)        hist: float2[BINS*TPB]
//   [61440, +24576)   xs:   float2[STAGES*TILE]
//   [86016, +12288)   ts:   int[STAGES*TILE]
#define SMEM_HIST 0
#define SMEM_XS   61440
#define SMEM_TS   (SMEM_XS + STAGES * TILE * 8)
#define SMEM_TOTAL (SMEM_TS + STAGES * TILE * 4)   // 98304 B = 96 KB

__device__ float2 g_part[GRID * BINS];
__device__ unsigned int g_ctr = 0;

__device__ __forceinline__ float rcp_approx(float x) {
    float r;
    asm("rcp.approx.f32 %0, %1;" : "=f"(r) : "f"(x));
    return r;
}

__device__ __forceinline__ void cp_async16(uint32_t saddr, const void* gptr) {
    asm volatile("cp.async.cg.shared.global [%0], [%1], 16;" :: "r"(saddr), "l"(gptr));
}
__device__ __forceinline__ void cp_commit() {
    asm volatile("cp.async.commit_group;");
}
template <int N>
__device__ __forceinline__ void cp_wait() {
    asm volatile("cp.async.wait_group %0;" :: "n"(N));
}

// Phase-A math only: u = x_other - x_true; bin = trunc(30*sigmoid(u)); ce = log(1+e^u).
__device__ __forceinline__ void ghm_math(float x0, float x1, int t,
                                         int* boff, float* ce) {
    float diff = x1 - x0;
    float u = __int_as_float(__float_as_int(diff) ^ (t << 31));
    float e = __expf(u);
    float s = 1.0f + e;
    float r = rcp_approx(s);
    float bin_f = fmaf(r, -30.0f, 30.0f);        // 30*g
    bin_f = fminf(bin_f, 29.0f);
    *boff = (int)bin_f * TPB;                    // element offset into hrow
    *ce = __log2f(s) * 0.69314718056f;
}

// issue cp.asyncs for tile T into stage st (predicated on T < NT); always commits.
__device__ __forceinline__ void issue_tile(const float4* __restrict__ x4,
                                           const int4* __restrict__ t4,
                                           int T, int NT, int st, int tid,
                                           uint32_t xs_s, uint32_t ts_s) {
    if (T < NT) {
        // x: TILE float2 = TILE/2 float4 = 512 -> 2 per thread
        const float4* xg = x4 + (size_t)T * (TILE / 2);
        uint32_t xd = xs_s + (uint32_t)(st * TILE) * 8u;
        #pragma unroll
        for (int j = 0; j < TILE / 2 / TPB; j++) {
            int i = tid + j * TPB;
            cp_async16(xd + i * 16u, xg + i);
        }
        // t: TILE ints = TILE/4 int4 = 256 -> 1 per thread (first 256 threads)
        const int4* tg = t4 + (size_t)T * (TILE / 4);
        uint32_t td = ts_s + (uint32_t)(st * TILE) * 4u;
        if (tid < TILE / 4) cp_async16(td + tid * 16u, tg + tid);
    }
    cp_commit();
}

__global__ void __launch_bounds__(TPB, 2) ghm_fused(const float4* __restrict__ x4,
                                                    const int4* __restrict__ t4,
                                                    const float2* __restrict__ x2,
                                                    const int* __restrict__ tgt,
                                                    int B,
                                                    float* __restrict__ out,
                                                    int out_size) {
    extern __shared__ char smem[];
    float2* hist = (float2*)(smem + SMEM_HIST);
    float2* xs   = (float2*)(smem + SMEM_XS);
    int*    ts   = (int*)(smem + SMEM_TS);
    uint32_t xs_s = (uint32_t)__cvta_generic_to_shared(xs);
    uint32_t ts_s = (uint32_t)__cvta_generic_to_shared(ts);

    int tid = threadIdx.x;
    int bx  = blockIdx.x;

    #pragma unroll
    for (int b = 0; b < BINS; b++) hist[b * TPB + tid] = make_float2(0.0f, 0.0f);
    __syncthreads();

    float2* hrow = &hist[tid];

    int NT = B / TILE;

    // prologue: fill all stages
    #pragma unroll
    for (int p = 0; p < STAGES; p++)
        issue_tile(x4, t4, bx + p * GRID, NT, p, tid, xs_s, ts_s);

    int st = 0;
    for (int k = 0; ; k++) {
        int T = bx + k * GRID;
        if (T >= NT) break;

        cp_wait<STAGES - 1>();
        __syncthreads();

        float2* xst = xs + st * TILE;
        int*    tst = ts + st * TILE;

        // Phase A: pure math, full ILP, no smem RMW
        int   boff[EPT];
        float cev[EPT];
        #pragma unroll
        for (int j = 0; j < EPT; j++) {
            int i = tid + j * TPB;
            float2 xv = xst[i];
            ghm_math(xv.x, xv.y, tst[i], &boff[j], &cev[j]);
        }
        // Phase B: serial RMW chain, decoupled from math
        #pragma unroll
        for (int j = 0; j < EPT; j++) {
            float2 h = hrow[boff[j]];
            h.x += 1.0f;
            h.y += cev[j];
            hrow[boff[j]] = h;
        }

        __syncthreads();
        issue_tile(x4, t4, bx + (k + STAGES) * GRID, NT, st, tid, xs_s, ts_s);
        st = (st + 1 == STAGES) ? 0 : st + 1;
    }
    cp_wait<0>();

    // tail (B % TILE == 0 for this shape, kept for generality)
    int gt = bx * TPB + tid;
    for (int j = NT * TILE + gt; j < B; j += GRID * TPB) {
        float2 xv = x2[j];
        int bo; float cv;
        ghm_math(xv.x, xv.y, tgt[j], &bo, &cv);
        float2 h = hrow[bo];
        h.x += 1.0f; h.y += cv;
        hrow[bo] = h;
    }

    __syncthreads();

    // tree-reduce columns per bin
    for (int s = TPB / 2; s > 0; s >>= 1) {
        if (tid < s) {
            #pragma unroll
            for (int b = 0; b < BINS; b++) {
                float2 p = hist[b * TPB + tid];
                float2 q = hist[b * TPB + tid + s];
                p.x += q.x; p.y += q.y;
                hist[b * TPB + tid] = p;
            }
        }
        __syncthreads();
    }

    // per-block partials + last-block finalize
    if (tid < BINS) g_part[bx * BINS + tid] = hist[tid * TPB];
    __threadfence();
    __syncthreads();

    __shared__ bool is_last;
    if (tid == 0) {
        unsigned prev = atomicAdd(&g_ctr, 1u);
        is_last = (prev == GRID - 1);
    }
    __syncthreads();
    if (!is_last) return;

    __threadfence();

    #pragma unroll
    for (int b = 0; b < BINS; b++) hist[b * TPB + tid] = make_float2(0.0f, 0.0f);
    __syncthreads();

    for (int i = tid; i < GRID * BINS; i += TPB) {
        float2 v = g_part[i];
        int b = i % BINS;
        float2 h = hrow[b * TPB];
        h.x += v.x; h.y += v.y;
        hrow[b * TPB] = h;
    }
    __syncthreads();

    for (int s = TPB / 2; s > 0; s >>= 1) {
        if (tid < s) {
            #pragma unroll
            for (int b = 0; b < BINS; b++) {
                float2 p = hist[b * TPB + tid];
                float2 q = hist[b * TPB + tid + s];
                p.x += q.x; p.y += q.y;
                hist[b * TPB + tid] = p;
            }
        }
        __syncthreads();
    }

    if (tid < 32) {
        float cnt = (tid < BINS) ? hist[tid * TPB].x : 0.0f;
        float ces = (tid < BINS) ? hist[tid * TPB].y : 0.0f;
        float nz   = (cnt > 0.0f) ? 1.0f : 0.0f;
        float term = (cnt > 0.0f) ? ces / (0.25f * cnt) : 0.0f;
        #pragma unroll
        for (int o = 16; o > 0; o >>= 1) {
            nz   += __shfl_xor_sync(0xFFFFFFFFu, nz,   o);
            term += __shfl_xor_sync(0xFFFFFFFFu, term, o);
        }
        if (tid == 0) {
            float loss = term / fmaxf(nz, 1.0f);
            for (int i = 0; i < out_size; i++) out[i] = loss;
            g_ctr = 0;  // reset for next graph replay
        }
    }
}

extern "C" void kernel_launch(void* const* d_in, const int* in_sizes, int n_in,
                              void* d_out, int out_size) {
    const float* x   = (const float*)d_in[0];
    const int*   tgt = (const int*)d_in[1];
    int B = in_sizes[1];   // target element count == batch size

    cudaFuncSetAttribute(ghm_fused, cudaFuncAttributeMaxDynamicSharedMemorySize, SMEM_TOTAL);
    ghm_fused<<<GRID, TPB, SMEM_TOTAL>>>((const float4*)x, (const int4*)tgt,
                                         (const float2*)x, tgt, B,
                                         (float*)d_out, out_size);
}

// round 10
// speedup vs baseline: 1.3053x; 1.0444x over previous
#include <cuda_runtime.h>
#include <cuda_bf16.h>
#include <cstdint>

#define BINS   30
#define TPB    256
#define GRID   296     // 2 blocks per SM
#define TILE   1024    // elements per tile (12 KB: 8 KB x + 4 KB t)
#define STAGES 3
#define EPT    4       // elements per thread per tile (thread owns 4*tid..4*tid+3)

// dynamic smem layout (bytes):
//   [0, 61440)        hist: float2[BINS*TPB]
//   [61440, +24576)   xs:   float2[STAGES*TILE]
//   [86016, +12288)   ts:   int[STAGES*TILE]
#define SMEM_HIST 0
#define SMEM_XS   61440
#define SMEM_TS   (SMEM_XS + STAGES * TILE * 8)
#define SMEM_TOTAL (SMEM_TS + STAGES * TILE * 4)   // 98304 B = 96 KB

__device__ float2 g_part[GRID * BINS];
__device__ unsigned int g_ctr = 0;

__device__ __forceinline__ float rcp_approx(float x) {
    float r;
    asm("rcp.approx.f32 %0, %1;" : "=f"(r) : "f"(x));
    return r;
}

__device__ __forceinline__ void cp_async16(uint32_t saddr, const void* gptr) {
    asm volatile("cp.async.cg.shared.global [%0], [%1], 16;" :: "r"(saddr), "l"(gptr));
}
__device__ __forceinline__ void cp_commit() {
    asm volatile("cp.async.commit_group;");
}
template <int N>
__device__ __forceinline__ void cp_wait() {
    asm volatile("cp.async.wait_group %0;" :: "n"(N));
}

// math only: u = x_other - x_true; bin = trunc(30*sigmoid(u)); ce = log(1+e^u).
__device__ __forceinline__ void ghm_math(float x0, float x1, int t,
                                         int* boff, float* ce) {
    float diff = x1 - x0;
    float u = __int_as_float(__float_as_int(diff) ^ (t << 31));
    float e = __expf(u);
    float s = 1.0f + e;
    float r = rcp_approx(s);
    float bin_f = fmaf(r, -30.0f, 30.0f);        // 30*g
    bin_f = fminf(bin_f, 29.0f);
    *boff = (int)bin_f * TPB;
    *ce = __log2f(s) * 0.69314718056f;
}

// thread-owned copy: this thread's 4 elements of tile T into stage st.
// x: float4 indices 2*tid, 2*tid+1 ; t: int4 index tid. Always commits.
__device__ __forceinline__ void issue_tile(const float4* __restrict__ x4,
                                           const int4* __restrict__ t4,
                                           int T, int NT, int st, int tid,
                                           uint32_t xs_s, uint32_t ts_s) {
    if (T < NT) {
        const float4* xg = x4 + (size_t)T * (TILE / 2) + 2 * tid;
        uint32_t xd = xs_s + (uint32_t)(st * TILE) * 8u + (uint32_t)tid * 32u;
        cp_async16(xd,       xg);
        cp_async16(xd + 16u, xg + 1);
        const int4* tg = t4 + (size_t)T * (TILE / 4) + tid;
        uint32_t td = ts_s + (uint32_t)(st * TILE) * 4u + (uint32_t)tid * 16u;
        cp_async16(td, tg);
    }
    cp_commit();
}

__global__ void __launch_bounds__(TPB, 2) ghm_fused(const float4* __restrict__ x4,
                                                    const int4* __restrict__ t4,
                                                    const float2* __restrict__ x2,
                                                    const int* __restrict__ tgt,
                                                    int B,
                                                    float* __restrict__ out,
                                                    int out_size) {
    extern __shared__ char smem[];
    float2* hist = (float2*)(smem + SMEM_HIST);
    float2* xs   = (float2*)(smem + SMEM_XS);
    int*    ts   = (int*)(smem + SMEM_TS);
    uint32_t xs_s = (uint32_t)__cvta_generic_to_shared(xs);
    uint32_t ts_s = (uint32_t)__cvta_generic_to_shared(ts);

    int tid = threadIdx.x;
    int bx  = blockIdx.x;

    #pragma unroll
    for (int b = 0; b < BINS; b++) hist[b * TPB + tid] = make_float2(0.0f, 0.0f);
    __syncthreads();

    float2* hrow = &hist[tid];

    int NT = B / TILE;

    // prologue: fill all stages (own region only)
    #pragma unroll
    for (int p = 0; p < STAGES; p++)
        issue_tile(x4, t4, bx + p * GRID, NT, p, tid, xs_s, ts_s);

    // barrier-free steady state: each thread reads only the bytes it copied.
    int st = 0;
    for (int k = 0; ; k++) {
        int T = bx + k * GRID;
        if (T >= NT) break;

        cp_wait<STAGES - 1>();   // own copies for tile k complete -> self-visible

        const float4* xst = (const float4*)(xs + st * TILE) + 2 * tid;  // own 4 float2
        const int4*   tst = (const int4*)(ts + st * TILE) + tid;        // own 4 ints
        float4 xa = xst[0];
        float4 xb = xst[1];
        int4   tv = tst[0];

        int   boff[EPT];
        float cev[EPT];
        ghm_math(xa.x, xa.y, tv.x, &boff[0], &cev[0]);
        ghm_math(xa.z, xa.w, tv.y, &boff[1], &cev[1]);
        ghm_math(xb.x, xb.y, tv.z, &boff[2], &cev[2]);
        ghm_math(xb.z, xb.w, tv.w, &boff[3], &cev[3]);

        #pragma unroll
        for (int j = 0; j < EPT; j++) {
            float2 h = hrow[boff[j]];
            h.x += 1.0f;
            h.y += cev[j];
            hrow[boff[j]] = h;
        }

        // refill own region of this stage (reads above already consumed)
        issue_tile(x4, t4, bx + (k + STAGES) * GRID, NT, st, tid, xs_s, ts_s);
        st = (st + 1 == STAGES) ? 0 : st + 1;
    }
    cp_wait<0>();

    // tail (B % TILE == 0 for this shape, kept for generality)
    int gt = bx * TPB + tid;
    for (int j = NT * TILE + gt; j < B; j += GRID * TPB) {
        float2 xv = x2[j];
        int bo; float cv;
        ghm_math(xv.x, xv.y, tgt[j], &bo, &cv);
        float2 h = hrow[bo];
        h.x += 1.0f; h.y += cv;
        hrow[bo] = h;
    }

    __syncthreads();

    // tree-reduce columns per bin
    for (int s = TPB / 2; s > 0; s >>= 1) {
        if (tid < s) {
            #pragma unroll
            for (int b = 0; b < BINS; b++) {
                float2 p = hist[b * TPB + tid];
                float2 q = hist[b * TPB + tid + s];
                p.x += q.x; p.y += q.y;
                hist[b * TPB + tid] = p;
            }
        }
        __syncthreads();
    }

    // per-block partials + last-block finalize
    if (tid < BINS) g_part[bx * BINS + tid] = hist[tid * TPB];
    __threadfence();
    __syncthreads();

    __shared__ bool is_last;
    if (tid == 0) {
        unsigned prev = atomicAdd(&g_ctr, 1u);
        is_last = (prev == GRID - 1);
    }
    __syncthreads();
    if (!is_last) return;

    __threadfence();

    #pragma unroll
    for (int b = 0; b < BINS; b++) hist[b * TPB + tid] = make_float2(0.0f, 0.0f);
    __syncthreads();

    for (int i = tid; i < GRID * BINS; i += TPB) {
        float2 v = g_part[i];
        int b = i % BINS;
        float2 h = hrow[b * TPB];
        h.x += v.x; h.y += v.y;
        hrow[b * TPB] = h;
    }
    __syncthreads();

    for (int s = TPB / 2; s > 0; s >>= 1) {
        if (tid < s) {
            #pragma unroll
            for (int b = 0; b < BINS; b++) {
                float2 p = hist[b * TPB + tid];
                float2 q = hist[b * TPB + tid + s];
                p.x += q.x; p.y += q.y;
                hist[b * TPB + tid] = p;
            }
        }
        __syncthreads();
    }

    if (tid < 32) {
        float cnt = (tid < BINS) ? hist[tid * TPB].x : 0.0f;
        float ces = (tid < BINS) ? hist[tid * TPB].y : 0.0f;
        float nz   = (cnt > 0.0f) ? 1.0f : 0.0f;
        float term = (cnt > 0.0f) ? ces / (0.25f * cnt) : 0.0f;
        #pragma unroll
        for (int o = 16; o > 0; o >>= 1) {
            nz   += __shfl_xor_sync(0xFFFFFFFFu, nz,   o);
            term += __shfl_xor_sync(0xFFFFFFFFu, term, o);
        }
        if (tid == 0) {
            float loss = term / fmaxf(nz, 1.0f);
            for (int i = 0; i < out_size; i++) out[i] = loss;
            g_ctr = 0;  // reset for next graph replay
        }
    }
}

extern "C" void kernel_launch(void* const* d_in, const int* in_sizes, int n_in,
                              void* d_out, int out_size) {
    const float* x   = (const float*)d_in[0];
    const int*   tgt = (const int*)d_in[1];
    int B = in_sizes[1];   // target element count == batch size

    cudaFuncSetAttribute(ghm_fused, cudaFuncAttributeMaxDynamicSharedMemorySize, SMEM_TOTAL);
    ghm_fused<<<GRID, TPB, SMEM_TOTAL>>>((const float4*)x, (const int4*)tgt,
                                         (const float2*)x, tgt, B,
                                         (float*)d_out, out_size);
}